// round 11
// baseline (speedup 1.0000x reference)
#include <cuda_runtime.h>

// Problem constants
#define S_GRID 14
#define NCLS   20
#define N_IMG  4096
#define CELLS  (N_IMG * S_GRID * S_GRID)   // 802816
#define PRED_C 30
#define TPB    256
#define CPT    2                            // cells per thread
#define NBLK   (CELLS / (TPB * CPT))        // 1568 (exact)

// Persistent device state. Zero-initialized at module load; the finalizing
// block resets it at the end of every launch, so each graph replay starts clean.
__device__ double g_acc[4];    // [0]=cls, [1]=noobj, [2]=containing, [3]=reg
__device__ unsigned int g_done;

struct Partials { float cls, noobj, cont, reg; };

// Compute the 4 loss partials for one cell from registers.
static __device__ __forceinline__ Partials cell_loss(
    const float* p, const float4 tb, const float4* tc, const float m)
{
    Partials r;

    // ---- class loss ----
    float s = 0.f;
    #pragma unroll
    for (int j = 0; j < NCLS / 4; j++) {
        const float q0 = p[10 + 4 * j + 0] - tc[j].x;
        const float q1 = p[10 + 4 * j + 1] - tc[j].y;
        const float q2 = p[10 + 4 * j + 2] - tc[j].z;
        const float q3 = p[10 + 4 * j + 3] - tc[j].w;
        s += q0 * q0 + q1 * q1 + q2 * q2 + q3 * q3;
    }
    r.cls = m * s;

    // ---- no-object loss ----
    const float c0 = p[4], c1 = p[9];
    r.noobj = (1.0f - m) * (c0 * c0 + c1 * c1);

    // ---- IoU per box (B=2) ----
    float iou[2];
    #pragma unroll
    for (int b = 0; b < 2; b++) {
        const float x = p[5 * b + 0] * (1.0f / S_GRID);
        const float y = p[5 * b + 1] * (1.0f / S_GRID);
        const float w = p[5 * b + 2];
        const float h = p[5 * b + 3];
        const float p1x = x - w * 0.5f, p1y = y - h * 0.5f;
        const float p2x = x + w * 0.5f, p2y = y + h * 0.5f;
        const float ltx = fmaxf(p1x, tb.x), lty = fmaxf(p1y, tb.y);
        const float rbx = fminf(p2x, tb.z), rby = fminf(p2y, tb.w);
        const float iw = fmaxf(rbx - ltx, 0.0f);
        const float ih = fmaxf(rby - lty, 0.0f);
        const float inter  = iw * ih;
        const float area_p = w * h;
        const float area_t = (tb.z - tb.x) * (tb.w - tb.y);
        iou[b] = inter / (area_p + area_t - inter);
    }

    // argmax over B=2 (first occurrence of max, like jnp.argmax)
    const bool pick1 = (iou[1] > iou[0]);
    const float bx = pick1 ? p[5] : p[0];
    const float by = pick1 ? p[6] : p[1];
    const float bw = pick1 ? p[7] : p[2];
    const float bh = pick1 ? p[8] : p[3];
    const float bc = pick1 ? p[9] : p[4];

    r.cont = m * (bc - 1.0f) * (bc - 1.0f);

    const float dx = bx - tb.x;
    const float dy = by - tb.y;
    const float dw = sqrtf(bw) - sqrtf(tb.z);
    const float dh = sqrtf(bh) - sqrtf(tb.w);
    r.reg = m * (dx * dx + dy * dy + dw * dw + dh * dh);
    return r;
}

__global__ void __launch_bounds__(TPB) yolo_fused_kernel(
    const float* __restrict__ pred,   // [CELLS, 30]
    const float* __restrict__ tbox,   // [CELLS, 4]
    const float* __restrict__ tcls,   // [CELLS, 20]
    const int*   __restrict__ mask,   // [CELLS]
    float*       __restrict__ out)    // [5]
{
    const int t  = threadIdx.x;
    const int i0 = blockIdx.x * (TPB * CPT) + t;   // cell A
    const int i1 = i0 + TPB;                        // cell B (same warp-coalesced pattern)

    // ============ front-batch ALL loads for BOTH cells (44 LDGs in flight) ============
    float pA[PRED_C], pB[PRED_C];
    {
        const float2* a2 = reinterpret_cast<const float2*>(pred + (size_t)i0 * PRED_C);
        const float2* b2 = reinterpret_cast<const float2*>(pred + (size_t)i1 * PRED_C);
        #pragma unroll
        for (int j = 0; j < PRED_C / 2; j++) {
            const float2 va = a2[j];
            const float2 vb = b2[j];
            pA[2 * j] = va.x; pA[2 * j + 1] = va.y;
            pB[2 * j] = vb.x; pB[2 * j + 1] = vb.y;
        }
    }
    const float4 tbA = reinterpret_cast<const float4*>(tbox)[i0];
    const float4 tbB = reinterpret_cast<const float4*>(tbox)[i1];

    float4 tcA[NCLS / 4], tcB[NCLS / 4];
    {
        const float4* a4 = reinterpret_cast<const float4*>(tcls + (size_t)i0 * NCLS);
        const float4* b4 = reinterpret_cast<const float4*>(tcls + (size_t)i1 * NCLS);
        #pragma unroll
        for (int j = 0; j < NCLS / 4; j++) { tcA[j] = a4[j]; tcB[j] = b4[j]; }
    }
    const float mA = (mask[i0] != 0) ? 1.0f : 0.0f;
    const float mB = (mask[i1] != 0) ? 1.0f : 0.0f;

    // ============ compute both cells, accumulate ============
    const Partials rA = cell_loss(pA, tbA, tcA, mA);
    const Partials rB = cell_loss(pB, tbB, tcB, mB);

    float cls_s   = rA.cls   + rB.cls;
    float noobj_s = rA.noobj + rB.noobj;
    float cont_s  = rA.cont  + rB.cont;
    float reg_s   = rA.reg   + rB.reg;

    // ============ reduction: warp shuffle, then across 8 warps ============
    #pragma unroll
    for (int off = 16; off > 0; off >>= 1) {
        cls_s   += __shfl_down_sync(0xFFFFFFFFu, cls_s,   off);
        noobj_s += __shfl_down_sync(0xFFFFFFFFu, noobj_s, off);
        cont_s  += __shfl_down_sync(0xFFFFFFFFu, cont_s,  off);
        reg_s   += __shfl_down_sync(0xFFFFFFFFu, reg_s,   off);
    }

    __shared__ float sh[4][8];  // 256 threads -> 8 warps
    const int wid = t >> 5;
    const int lid = t & 31;
    if (lid == 0) {
        sh[0][wid] = cls_s;
        sh[1][wid] = noobj_s;
        sh[2][wid] = cont_s;
        sh[3][wid] = reg_s;
    }
    __syncthreads();

    if (wid == 0) {
        float v0 = (lid < 8) ? sh[0][lid] : 0.f;
        float v1 = (lid < 8) ? sh[1][lid] : 0.f;
        float v2 = (lid < 8) ? sh[2][lid] : 0.f;
        float v3 = (lid < 8) ? sh[3][lid] : 0.f;
        #pragma unroll
        for (int off = 4; off > 0; off >>= 1) {
            v0 += __shfl_down_sync(0xFFFFFFFFu, v0, off);
            v1 += __shfl_down_sync(0xFFFFFFFFu, v1, off);
            v2 += __shfl_down_sync(0xFFFFFFFFu, v2, off);
            v3 += __shfl_down_sync(0xFFFFFFFFu, v3, off);
        }
        if (lid == 0) {
            atomicAdd(&g_acc[0], (double)v0);
            atomicAdd(&g_acc[1], (double)v1);
            atomicAdd(&g_acc[2], (double)v2);
            atomicAdd(&g_acc[3], (double)v3);

            __threadfence();
            const unsigned int old = atomicAdd(&g_done, 1u);
            if (old == (unsigned int)(gridDim.x - 1)) {
                // Last block: finalize + reset for the next graph replay.
                const double cls_t   = atomicAdd(&g_acc[0], 0.0);
                const double noobj_t = atomicAdd(&g_acc[1], 0.0);
                const double cont_t  = atomicAdd(&g_acc[2], 0.0);
                const double reg_t   = atomicAdd(&g_acc[3], 0.0);
                const double inv_n = 1.0 / (double)N_IMG;
                const double cls   = cls_t   * inv_n;
                const double noobj = noobj_t * inv_n;
                const double cont  = cont_t  * inv_n;
                const double reg   = reg_t   * inv_n;
                out[0] = (float)(cls + 0.5 * noobj + 5.0 * reg + cont);
                out[1] = (float)reg;
                out[2] = (float)cont;
                out[3] = (float)noobj;
                out[4] = (float)cls;
                g_acc[0] = 0.0; g_acc[1] = 0.0; g_acc[2] = 0.0; g_acc[3] = 0.0;
                __threadfence();
                g_done = 0u;
            }
        }
    }
}

extern "C" void kernel_launch(void* const* d_in, const int* in_sizes, int n_in,
                              void* d_out, int out_size) {
    // Identify inputs by element count (robust to ordering):
    //   pred: 24,084,480   tbox: 3,211,264   tcls: 16,056,320   mask: 802,816
    const float* pred = nullptr;
    const float* tbox = nullptr;
    const float* tcls = nullptr;
    const int*   msk  = nullptr;
    for (int k = 0; k < n_in; k++) {
        const long long sz = in_sizes[k];
        if      (sz == (long long)CELLS * PRED_C) pred = (const float*)d_in[k];
        else if (sz == (long long)CELLS * 4)      tbox = (const float*)d_in[k];
        else if (sz == (long long)CELLS * NCLS)   tcls = (const float*)d_in[k];
        else if (sz == (long long)CELLS)          msk  = (const int*)d_in[k];
    }
    float* out = (float*)d_out;

    yolo_fused_kernel<<<NBLK, TPB>>>(pred, tbox, tcls, msk, out);
}

// round 12
// speedup vs baseline: 1.4099x; 1.4099x over previous
#include <cuda_runtime.h>

// Problem constants
#define S_GRID 14
#define NCLS   20
#define N_IMG  4096
#define CELLS  (N_IMG * S_GRID * S_GRID)   // 802816
#define PRED_C 30
#define TPB    256
#define NBLK   (CELLS / TPB)               // 3136 (exact)

// Persistent accumulators. Zero at module load; finalize kernel resets them
// after reading, so every graph replay starts clean. No done-counter, no
// threadfence: the graph edge between the two kernels provides ordering.
__device__ double g_acc[4];    // [0]=cls, [1]=noobj, [2]=containing, [3]=reg

__global__ void __launch_bounds__(TPB) yolo_main_kernel(
    const float* __restrict__ pred,   // [CELLS, 30]
    const float* __restrict__ tbox,   // [CELLS, 4]
    const float* __restrict__ tcls,   // [CELLS, 20]
    const int*   __restrict__ mask)   // [CELLS]
{
    const int i = blockIdx.x * TPB + threadIdx.x;

    // ---- per-cell loads (ptxas schedules; regs=32 variant measured fastest) ----
    float p[PRED_C];
    {
        const float2* p2 = reinterpret_cast<const float2*>(pred + (size_t)i * PRED_C);
        #pragma unroll
        for (int j = 0; j < PRED_C / 2; j++) {
            const float2 v = p2[j];
            p[2 * j]     = v.x;
            p[2 * j + 1] = v.y;
        }
    }
    const float4 tb = reinterpret_cast<const float4*>(tbox)[i];

    float4 tc[NCLS / 4];
    {
        const float4* tc4 = reinterpret_cast<const float4*>(tcls + (size_t)i * NCLS);
        #pragma unroll
        for (int j = 0; j < NCLS / 4; j++) tc[j] = tc4[j];
    }
    const float m = (mask[i] != 0) ? 1.0f : 0.0f;

    // ---- class loss: m * sum (pred_cls - target_cls)^2 ----
    float s = 0.f;
    #pragma unroll
    for (int j = 0; j < NCLS / 4; j++) {
        const float q0 = p[10 + 4 * j + 0] - tc[j].x;
        const float q1 = p[10 + 4 * j + 1] - tc[j].y;
        const float q2 = p[10 + 4 * j + 2] - tc[j].z;
        const float q3 = p[10 + 4 * j + 3] - tc[j].w;
        s += q0 * q0 + q1 * q1 + q2 * q2 + q3 * q3;
    }
    float cls_s = m * s;

    // ---- no-object loss: (1-m) * sum_b conf_b^2 ----
    const float c0 = p[4], c1 = p[9];
    float noobj_s = (1.0f - m) * (c0 * c0 + c1 * c1);

    // ---- IoU per box (B=2) ----
    float iou[2];
    #pragma unroll
    for (int b = 0; b < 2; b++) {
        const float x = p[5 * b + 0] * (1.0f / S_GRID);
        const float y = p[5 * b + 1] * (1.0f / S_GRID);
        const float w = p[5 * b + 2];
        const float h = p[5 * b + 3];
        const float p1x = x - w * 0.5f, p1y = y - h * 0.5f;
        const float p2x = x + w * 0.5f, p2y = y + h * 0.5f;
        const float ltx = fmaxf(p1x, tb.x), lty = fmaxf(p1y, tb.y);
        const float rbx = fminf(p2x, tb.z), rby = fminf(p2y, tb.w);
        const float iw = fmaxf(rbx - ltx, 0.0f);
        const float ih = fmaxf(rby - lty, 0.0f);
        const float inter  = iw * ih;
        const float area_p = w * h;
        const float area_t = (tb.z - tb.x) * (tb.w - tb.y);
        iou[b] = inter / (area_p + area_t - inter);
    }

    // argmax over B=2 (first occurrence of max, like jnp.argmax)
    const bool pick1 = (iou[1] > iou[0]);
    const float bx = pick1 ? p[5] : p[0];
    const float by = pick1 ? p[6] : p[1];
    const float bw = pick1 ? p[7] : p[2];
    const float bh = pick1 ? p[8] : p[3];
    const float bc = pick1 ? p[9] : p[4];

    // ---- containing-object loss ----
    float cont_s = m * (bc - 1.0f) * (bc - 1.0f);

    // ---- regression loss (center + dim) ----
    const float dx = bx - tb.x;
    const float dy = by - tb.y;
    const float dw = sqrtf(bw) - sqrtf(tb.z);
    const float dh = sqrtf(bh) - sqrtf(tb.w);
    float reg_s = m * (dx * dx + dy * dy + dw * dw + dh * dh);

    // ---- reduction: warp shuffle, then across 8 warps ----
    #pragma unroll
    for (int off = 16; off > 0; off >>= 1) {
        cls_s   += __shfl_down_sync(0xFFFFFFFFu, cls_s,   off);
        noobj_s += __shfl_down_sync(0xFFFFFFFFu, noobj_s, off);
        cont_s  += __shfl_down_sync(0xFFFFFFFFu, cont_s,  off);
        reg_s   += __shfl_down_sync(0xFFFFFFFFu, reg_s,   off);
    }

    __shared__ float sh[4][8];  // 256 threads -> 8 warps
    const int wid = threadIdx.x >> 5;
    const int lid = threadIdx.x & 31;
    if (lid == 0) {
        sh[0][wid] = cls_s;
        sh[1][wid] = noobj_s;
        sh[2][wid] = cont_s;
        sh[3][wid] = reg_s;
    }
    __syncthreads();

    if (wid == 0) {
        float v0 = (lid < 8) ? sh[0][lid] : 0.f;
        float v1 = (lid < 8) ? sh[1][lid] : 0.f;
        float v2 = (lid < 8) ? sh[2][lid] : 0.f;
        float v3 = (lid < 8) ? sh[3][lid] : 0.f;
        #pragma unroll
        for (int off = 4; off > 0; off >>= 1) {
            v0 += __shfl_down_sync(0xFFFFFFFFu, v0, off);
            v1 += __shfl_down_sync(0xFFFFFFFFu, v1, off);
            v2 += __shfl_down_sync(0xFFFFFFFFu, v2, off);
            v3 += __shfl_down_sync(0xFFFFFFFFu, v3, off);
        }
        if (lid == 0) {
            // Fire-and-forget: results unused -> compiler emits no-return RED.
            // Block retires without waiting on the L2 round trip.
            atomicAdd(&g_acc[0], (double)v0);
            atomicAdd(&g_acc[1], (double)v1);
            atomicAdd(&g_acc[2], (double)v2);
            atomicAdd(&g_acc[3], (double)v3);
        }
    }
}

__global__ void yolo_finalize_kernel(float* __restrict__ out) {
    // Runs after the main kernel (graph edge = device-wide ordering).
    const double cls_t   = g_acc[0];
    const double noobj_t = g_acc[1];
    const double cont_t  = g_acc[2];
    const double reg_t   = g_acc[3];
    const double inv_n = 1.0 / (double)N_IMG;
    const double cls   = cls_t   * inv_n;
    const double noobj = noobj_t * inv_n;
    const double cont  = cont_t  * inv_n;
    const double reg   = reg_t   * inv_n;
    out[0] = (float)(cls + 0.5 * noobj + 5.0 * reg + cont);
    out[1] = (float)reg;
    out[2] = (float)cont;
    out[3] = (float)noobj;
    out[4] = (float)cls;
    // Reset for the next graph replay.
    g_acc[0] = 0.0; g_acc[1] = 0.0; g_acc[2] = 0.0; g_acc[3] = 0.0;
}

extern "C" void kernel_launch(void* const* d_in, const int* in_sizes, int n_in,
                              void* d_out, int out_size) {
    // Identify inputs by element count (robust to ordering):
    //   pred: 24,084,480   tbox: 3,211,264   tcls: 16,056,320   mask: 802,816
    const float* pred = nullptr;
    const float* tbox = nullptr;
    const float* tcls = nullptr;
    const int*   msk  = nullptr;
    for (int k = 0; k < n_in; k++) {
        const long long sz = in_sizes[k];
        if      (sz == (long long)CELLS * PRED_C) pred = (const float*)d_in[k];
        else if (sz == (long long)CELLS * 4)      tbox = (const float*)d_in[k];
        else if (sz == (long long)CELLS * NCLS)   tcls = (const float*)d_in[k];
        else if (sz == (long long)CELLS)          msk  = (const int*)d_in[k];
    }
    float* out = (float*)d_out;

    yolo_main_kernel<<<NBLK, TPB>>>(pred, tbox, tcls, msk);
    yolo_finalize_kernel<<<1, 1>>>(out);
}